// round 10
// baseline (speedup 1.0000x reference)
#include <cuda_runtime.h>
#include <math.h>

#define NBATCH 1024
#define NSEQ   200
#define NROWS  (NBATCH*NSEQ)   /* 204800 */

/* ------------ static scratch (no allocations allowed) ------------ */
__device__ float g_enc [NROWS*128];           /* encoder output                    */
__device__ float g_xpre[NROWS*1024];          /* gate preacts, [r][h8*128 + u*4+g] */
__device__ float g_hseq[NSEQ*NBATCH*256];     /* hx per step (output GEMM input)   */
__device__ float g_hseqT[2][256*NBATCH];      /* transposed hx, parity-buffered    */
__device__ float g_predpart[2][8*NBATCH*2];   /* parity-buffered pred partials     */

typedef unsigned long long u64;

__device__ __forceinline__ u64 pack2(float lo, float hi){
    u64 r; asm("mov.b64 %0,{%1,%2};" : "=l"(r) : "f"(lo), "f"(hi)); return r;
}
__device__ __forceinline__ void unpack2(u64 v, float& lo, float& hi){
    asm("mov.b64 {%0,%1},%2;" : "=f"(lo), "=f"(hi) : "l"(v));
}
__device__ __forceinline__ u64 fma2(u64 a, u64 b, u64 c){
    u64 d; asm("fma.rn.f32x2 %0,%1,%2,%3;" : "=l"(d) : "l"(a), "l"(b), "l"(c)); return d;
}
__device__ __forceinline__ float sigmoidf_(float x){
    return __fdividef(1.0f, 1.0f + __expf(-x));
}

/* ================= Kernel 1: per-(b,t) set encoder ================= */
__global__ void enc_kernel(const float* __restrict__ coords,
                           const float* __restrict__ W_e1, const float* __restrict__ b_e1,
                           const float* __restrict__ W_e2, const float* __restrict__ b_e2)
{
    int rl = threadIdx.x >> 6;
    int j  = threadIdx.x & 63;
    size_t r = (size_t)blockIdx.x * 4 + rl;

    __shared__ float pt[4][44];
    __shared__ float m [4][2][64];

    if (j < 44) pt[rl][j] = coords[r*88 + ((j>>1)<<2) + (j&1)];
    __syncthreads();

    float w0 = W_e1[j], w1 = W_e1[64+j], bb = b_e1[j];
    float s1 = 0.f, s2 = 0.f;
#pragma unroll
    for (int p = 0; p < 11; p++){
        float hh = fmaf(pt[rl][2*p+1], w1, fmaf(pt[rl][2*p], w0, bb));
        s1 += fmaxf(hh, 0.f);
    }
#pragma unroll
    for (int p = 11; p < 22; p++){
        float hh = fmaf(pt[rl][2*p+1], w1, fmaf(pt[rl][2*p], w0, bb));
        s2 += fmaxf(hh, 0.f);
    }
    m[rl][0][j] = s1 * (1.0f/11.0f);
    m[rl][1][j] = s2 * (1.0f/11.0f);
    __syncthreads();

    float o1 = b_e2[j], o2 = b_e2[j];
#pragma unroll
    for (int k = 0; k < 64; k++){
        float w = W_e2[k*64 + j];
        o1 = fmaf(m[rl][0][k], w, o1);
        o2 = fmaf(m[rl][1][k], w, o2);
    }
    g_enc[r*128 + j]      = o1;
    g_enc[r*128 + 64 + j] = o2;
}

/* ================= Kernel 2: Xpre GEMM =================
   Output layout: g_xpre[r][h8*128 + u_local*4 + g], u_local 0..31.    */
__global__ void __launch_bounds__(256) xpre_kernel(
    const float* __restrict__ coords, const float* __restrict__ W_ih,
    const float* __restrict__ b_ih,   const float* __restrict__ b_hh)
{
    extern __shared__ float smx[];
    float* a_s = smx;            /* 32*132 = 4224 */
    float* w_s = a_s + 4224;     /* 32*64  = 2048 */
    float* epi = w_s + 2048;     /* 128*65 = 8320 */

    int h  = blockIdx.x;                 /* h16: 16 tiles of 16 units */
    size_t m0 = (size_t)blockIdx.y * 128;
    int tid = threadIdx.x;
    int tb = tid & 31, tu = tid >> 5;

    u64 acc2[4][4];
#pragma unroll
    for (int bi=0;bi<4;bi++)
#pragma unroll
        for (int g=0;g<4;g++) acc2[bi][g] = 0ULL;

    for (int k0 = 0; k0 < 172; k0 += 32){
#pragma unroll
        for (int i = 0; i < 16; i++){
            int li  = tid + i*256;
            int kk  = li & 31, row = li >> 5;
            int k   = k0 + kk;
            float v = 0.f;
            size_t r = m0 + row;
            if (k < 44)       v = coords[r*88 + ((k>>1)<<2) + (k&1)];
            else if (k < 172) v = g_enc[r*128 + (k-44)];
            a_s[kk*132 + row] = v;
        }
#pragma unroll
        for (int i = 0; i < 8; i++){
            int li = tid + i*256;
            int c  = li & 63, kk = li >> 6;
            int k  = k0 + kk;
            float v = 0.f;
            if (k < 172){
                int col = ((c>>4)<<8) + (h<<4) + (c&15);
                v = W_ih[k*1024 + col];
            }
            w_s[kk*64 + c] = v;
        }
        __syncthreads();
#pragma unroll
        for (int kk = 0; kk < 32; kk++){
            float4 a = *(const float4*)&a_s[kk*132 + 4*tb];
            u64 ax = pack2(a.x,a.x), ay = pack2(a.y,a.y);
            u64 az = pack2(a.z,a.z), aw = pack2(a.w,a.w);
            int kw = kk*64 + (tu<<1);
#pragma unroll
            for (int g = 0; g < 4; g++){
                u64 w2 = *(const u64*)&w_s[kw + g*16];
                acc2[0][g] = fma2(ax, w2, acc2[0][g]);
                acc2[1][g] = fma2(ay, w2, acc2[1][g]);
                acc2[2][g] = fma2(az, w2, acc2[2][g]);
                acc2[3][g] = fma2(aw, w2, acc2[3][g]);
            }
        }
        __syncthreads();
    }

#pragma unroll
    for (int g = 0; g < 4; g++){
        int col0 = (g<<8) + (h<<4) + 2*tu;
        float b0 = b_ih[col0]   + b_hh[col0];
        float b1 = b_ih[col0+1] + b_hh[col0+1];
#pragma unroll
        for (int bi = 0; bi < 4; bi++){
            float lo, hi; unpack2(acc2[bi][g], lo, hi);
            epi[(4*tb+bi)*65 + g*16 + 2*tu]     = lo + b0;
            epi[(4*tb+bi)*65 + g*16 + 2*tu + 1] = hi + b1;
        }
    }
    __syncthreads();
#pragma unroll
    for (int i = 0; i < 8; i++){
        int li = tid + i*256;            /* 2048 = 128 rows x 16 units */
        int row = li >> 4, j = li & 15;
        size_t r = m0 + row;
        int colp = (h>>1)*128 + ((h&1)*16 + j)*4;
        float4 v = make_float4(epi[row*65 +      j], epi[row*65 + 16 + j],
                               epi[row*65 + 32 + j], epi[row*65 + 48 + j]);
        *(float4*)&g_xpre[r*1024 + colp] = v;
    }
}

/* ================= Kernel 3: persistent cluster recurrence =================
   grid (8,16): 16 independent 8-CTA clusters (one per 64-row batch tile).
   CTA (h, bm): 64 rows x 32 units; 512 threads; thread: 4 rows x 1 unit.
   W_hh in SMEM once; cx in registers for all 200 steps; xpre prefetched
   into registers ahead of the GEMM. Cross-CTA hx/pred exchange through
   L2 globals, ordered ONLY by the cluster barrier (arrive=release,
   wait=acquire, cluster scope; cluster.sync flushes L1D). No fences.    */
#define RNN_SMEM_FLOATS (32768 + 256*64 + 64 + 64 + 64 + 64)

__global__ void __launch_bounds__(512,1) __cluster_dims__(8,1,1)
rnn_all_kernel(const float* __restrict__ coords, const float* __restrict__ W_ih,
               const float* __restrict__ W_hh,   const float* __restrict__ W_out,
               const float* __restrict__ b_out,  const float* __restrict__ pitch)
{
    extern __shared__ float sm[];
    float* w_s   = sm;                     /* [256][128] c=u*4+g : 32768 f */
    float* hx_s  = w_s + 32768;            /* [256][64]          : 16384 f */
    float* epi   = hx_s;                   /* overlay, [row*33+u]          */
    float* wo_s  = hx_s + 16384;           /* [32][2] */
    float* clo_s = wo_s + 64;
    float* px_s  = clo_s + 64;
    float* py_s  = px_s + 64;

    int h = blockIdx.x, bm = blockIdx.y;
    int tid = threadIdx.x;
    int u  = tid >> 4;                     /* unit 0..31      */
    int rb = tid & 15;                     /* row-block (x4)  */

    /* ---- one-time: W_hh slice -> smem [k][u*4+g] ---- */
#pragma unroll
    for (int i = 0; i < 16; i++){
        int li = tid + i*512;              /* 8192 f4 = 256 k x 32 c4 */
        int k = li >> 5, c4 = li & 31;
        int g = c4 >> 3, u0 = (c4 & 7) * 4;
        float4 v = *(const float4*)&W_hh[k*1024 + g*256 + h*32 + u0];
        w_s[k*128 + (u0+0)*4 + g] = v.x;
        w_s[k*128 + (u0+1)*4 + g] = v.y;
        w_s[k*128 + (u0+2)*4 + g] = v.z;
        w_s[k*128 + (u0+3)*4 + g] = v.w;
    }
    if (tid < 64){
        int uu = tid >> 1, d = tid & 1;
        wo_s[tid] = W_out[((size_t)(h*32+uu))*90 + 88 + d];
    }
    float cw[3][4];
#pragma unroll
    for (int j = 0; j < 3; j++)
#pragma unroll
        for (int g = 0; g < 4; g++)
            cw[j][g] = W_ih[(172+j)*1024 + g*256 + h*32 + u];

    float ps0 = pitch[0], ps1 = pitch[1];
    float bo88 = b_out[88], bo89 = b_out[89];

    float cx[4];
#pragma unroll
    for (int r = 0; r < 4; r++) cx[r] = 0.f;

    __syncthreads();

    for (int t = 0; t < NSEQ; t++){
        /* ---- pred + closest distance (per batch row) ---- */
        if (tid < 64){
            int bg = bm*64 + tid;
            float px = 0.f, py = 0.f;
            if (t > 0){
                const float* pp = g_predpart[(t-1)&1];
#pragma unroll
                for (int hh = 0; hh < 8; hh++){
                    float2 v = __ldcg((const float2*)&pp[((size_t)hh*NBATCH + bg)*2]);
                    px += v.x; py += v.y;
                }
                px = (px + bo88) * ps0;
                py = (py + bo89) * ps1;
            }
            const float* cp = coords + ((size_t)bg*NSEQ + t)*88;
            float md = 3.402823e38f;
#pragma unroll
            for (int p = 0; p < 22; p++){
                float dx = px - __ldg(&cp[4*p]), dy = py - __ldg(&cp[4*p+1]);
                md = fminf(md, fmaf(dx,dx,dy*dy));
            }
            clo_s[tid] = sqrtf(md);
            px_s[tid] = px; py_s[tid] = py;
        }

        /* ---- prefetch xpre tile into registers (hidden behind GEMM) ---- */
        float4 xv[4];
#pragma unroll
        for (int r = 0; r < 4; r++){
            size_t rglob = ((size_t)(bm*64 + rb*4 + r))*NSEQ + t;
            xv[r] = __ldcg((const float4*)&g_xpre[rglob*1024 + h*128 + u*4]);
        }

        u64 acc[2][4];
#pragma unroll
        for (int rp=0;rp<2;rp++)
#pragma unroll
            for (int g=0;g<4;g++) acc[rp][g] = 0ULL;

        if (t > 0){
            /* ---- stage hx (all K) from transposed buffer, coalesced ---- */
            const float* hT = g_hseqT[(t-1)&1] + bm*64;
#pragma unroll
            for (int i = 0; i < 16; i++){
                int li = tid + i*512;      /* 8192 f2 = 256 k x 32 pairs */
                int k = li >> 5, l = li & 31;
                float2 v = __ldcg((const float2*)&hT[k*1024 + 2*l]);
                *(float2*)&hx_s[k*64 + 2*l] = v;
            }
            __syncthreads();

            /* ---- GEMM: 256 kk ---- */
            const float* hbase = hx_s + rb*4;
            const float* wbase = w_s + u*4;
#pragma unroll 8
            for (int kk = 0; kk < 256; kk++){
                ulonglong2 A = *(const ulonglong2*)(hbase + kk*64);
                float4 wv = *(const float4*)(wbase + kk*128);
                u64 w0 = pack2(wv.x, wv.x), w1 = pack2(wv.y, wv.y);
                u64 w2 = pack2(wv.z, wv.z), w3 = pack2(wv.w, wv.w);
                acc[0][0] = fma2(A.x, w0, acc[0][0]);
                acc[0][1] = fma2(A.x, w1, acc[0][1]);
                acc[0][2] = fma2(A.x, w2, acc[0][2]);
                acc[0][3] = fma2(A.x, w3, acc[0][3]);
                acc[1][0] = fma2(A.y, w0, acc[1][0]);
                acc[1][1] = fma2(A.y, w1, acc[1][1]);
                acc[1][2] = fma2(A.y, w2, acc[1][2]);
                acc[1][3] = fma2(A.y, w3, acc[1][3]);
            }
        }
        __syncthreads();   /* clo_s ready (t=0) / hx_s reads done -> epi safe */

        /* ---- LSTM pointwise; cx in registers across steps ---- */
#pragma unroll
        for (int r = 0; r < 4; r++){
            int row = rb*4 + r;
            float clo = clo_s[row], ppx = px_s[row], ppy = py_s[row];
            float lo0, hi0, lo1, hi1, lo2, hi2, lo3, hi3;
            unpack2(acc[r>>1][0], lo0, hi0);
            unpack2(acc[r>>1][1], lo1, hi1);
            unpack2(acc[r>>1][2], lo2, hi2);
            unpack2(acc[r>>1][3], lo3, hi3);
            float gi = (r&1) ? hi0 : lo0;
            float gf = (r&1) ? hi1 : lo1;
            float gg = (r&1) ? hi2 : lo2;
            float go = (r&1) ? hi3 : lo3;
            gi += xv[r].x + clo*cw[0][0] + ppx*cw[1][0] + ppy*cw[2][0];
            gf += xv[r].y + clo*cw[0][1] + ppx*cw[1][1] + ppy*cw[2][1];
            gg += xv[r].z + clo*cw[0][2] + ppx*cw[1][2] + ppy*cw[2][2];
            go += xv[r].w + clo*cw[0][3] + ppx*cw[1][3] + ppy*cw[2][3];
            float c2 = sigmoidf_(gf)*cx[r] + sigmoidf_(gi)*tanhf(gg);
            float h2 = sigmoidf_(go)*tanhf(c2);
            cx[r] = c2;
            epi[row*33 + u] = h2;
        }
        __syncthreads();

        /* ---- plain hseq store [t][b][256] ---- */
        {
            float* hout = g_hseq + ((size_t)t*NBATCH + bm*64)*256 + h*32;
#pragma unroll
            for (int i = 0; i < 4; i++){
                int li = tid + i*512;      /* 2048 = 64 rows x 32 c */
                int row = li >> 5, c = li & 31;
                hout[row*256 + c] = epi[row*33 + c];
            }
        }
        /* ---- transposed hseqT store [t&1][col][1024] ---- */
        {
            float* hT2 = g_hseqT[t&1] + bm*64;
#pragma unroll
            for (int i = 0; i < 4; i++){
                int li = tid + i*512;      /* 2048 = 32 cols x 64 rows */
                int col = li >> 6, row = li & 63;
                hT2[(size_t)(h*32 + col)*1024 + row] = epi[row*33 + col];
            }
        }
        /* ---- pred partials for step t+1 ---- */
        if (tid < 64){
            int bg = bm*64 + tid;
            float px = 0.f, py = 0.f;
#pragma unroll
            for (int uu = 0; uu < 32; uu++){
                float hv = epi[tid*33 + uu];
                px = fmaf(hv, wo_s[2*uu],   px);
                py = fmaf(hv, wo_s[2*uu+1], py);
            }
            *(float2*)&g_predpart[t&1][((size_t)h*NBATCH + bg)*2] = make_float2(px, py);
        }

        /* ---- cluster barrier: arrive(release) + wait(acquire), no fence ---- */
        asm volatile("barrier.cluster.arrive.aligned;" ::: "memory");
        asm volatile("barrier.cluster.wait.aligned;"   ::: "memory");
    }
}

/* ================= Kernel 4: output head GEMM ================= */
__global__ void __launch_bounds__(256) out_kernel(
    const float* __restrict__ W_out, const float* __restrict__ b_out,
    const float* __restrict__ pitch, float* __restrict__ out)
{
    size_t r0 = (size_t)blockIdx.x * 64;
    int tid = threadIdx.x;
    int tx = tid & 15, ty = tid >> 4;

    __shared__ float a_s[32*68];
    __shared__ float w_s[32*96];

    float acc[4][6];
#pragma unroll
    for (int bi=0;bi<4;bi++)
#pragma unroll
        for (int ci=0;ci<6;ci++) acc[bi][ci]=0.f;

    for (int k0 = 0; k0 < 256; k0 += 32){
#pragma unroll
        for (int i = 0; i < 8; i++){
            int li = tid + i*256;
            int kk = li & 31, row = li >> 5;
            size_t r = r0 + row;
            int t = (int)(r % NSEQ), b = (int)(r / NSEQ);
            a_s[kk*68 + row] = g_hseq[((size_t)t*NBATCH + b)*256 + k0 + kk];
        }
#pragma unroll
        for (int i = 0; i < 12; i++){
            int li = tid + i*256;
            int n = li % 96, kk = li / 96;
            w_s[kk*96 + n] = (n < 90) ? W_out[(k0+kk)*90 + n] : 0.f;
        }
        __syncthreads();
#pragma unroll
        for (int kk = 0; kk < 32; kk++){
            float4 a = *(const float4*)&a_s[kk*68 + 4*ty];
            float w[6];
#pragma unroll
            for (int ci = 0; ci < 6; ci++) w[ci] = w_s[kk*96 + 6*tx + ci];
#pragma unroll
            for (int ci = 0; ci < 6; ci++){
                acc[0][ci] = fmaf(a.x, w[ci], acc[0][ci]);
                acc[1][ci] = fmaf(a.y, w[ci], acc[1][ci]);
                acc[2][ci] = fmaf(a.z, w[ci], acc[2][ci]);
                acc[3][ci] = fmaf(a.w, w[ci], acc[3][ci]);
            }
        }
        __syncthreads();
    }
#pragma unroll
    for (int bi = 0; bi < 4; bi++){
        size_t r = r0 + 4*ty + bi;
#pragma unroll
        for (int ci = 0; ci < 6; ci++){
            int n = 6*tx + ci;
            if (n < 90)
                out[r*90 + n] = (acc[bi][ci] + b_out[n]) * pitch[n & 1];
        }
    }
}

/* ================= host launcher ================= */
extern "C" void kernel_launch(void* const* d_in, const int* in_sizes, int n_in,
                              void* d_out, int out_size)
{
    const float* coords = (const float*)d_in[0];
    const float* pitch  = (const float*)d_in[1];
    const float* W_e1   = (const float*)d_in[2];
    const float* b_e1   = (const float*)d_in[3];
    const float* W_e2   = (const float*)d_in[4];
    const float* b_e2   = (const float*)d_in[5];
    const float* W_ih   = (const float*)d_in[6];
    const float* b_ih   = (const float*)d_in[7];
    const float* W_hh   = (const float*)d_in[8];
    const float* b_hh   = (const float*)d_in[9];
    const float* W_out  = (const float*)d_in[10];
    const float* b_out  = (const float*)d_in[11];
    float* out = (float*)d_out;

    size_t xpre_smem = 14592u * sizeof(float);                  /*  58,368 B */
    size_t rnn_smem  = (size_t)RNN_SMEM_FLOATS * sizeof(float); /* 197,632 B */
    static int attr_done = 0;
    if (!attr_done){
        cudaFuncSetAttribute(xpre_kernel, cudaFuncAttributeMaxDynamicSharedMemorySize,
                             (int)xpre_smem);
        cudaFuncSetAttribute(rnn_all_kernel, cudaFuncAttributeMaxDynamicSharedMemorySize,
                             (int)rnn_smem);
        attr_done = 1;
    }

    enc_kernel<<<NROWS/4, 256>>>(coords, W_e1, b_e1, W_e2, b_e2);
    xpre_kernel<<<dim3(16, NROWS/128), 256, xpre_smem>>>(coords, W_ih, b_ih, b_hh);
    rnn_all_kernel<<<dim3(8,16), 512, rnn_smem>>>(coords, W_ih, W_hh, W_out, b_out, pitch);
    out_kernel<<<NROWS/64, 256>>>(W_out, b_out, pitch, out);
}

// round 14
// speedup vs baseline: 1.3430x; 1.3430x over previous
#include <cuda_runtime.h>
#include <math.h>

#define NBATCH 1024
#define NSEQ   200
#define NROWS  (NBATCH*NSEQ)   /* 204800 */

/* ------------ static scratch (no allocations allowed) ------------ */
__device__ float g_enc [NROWS*128];           /* encoder output                    */
__device__ float g_xpre[NROWS*1024];          /* gate preacts, [r][h8*128 + u*4+g] */
__device__ float g_hseq[NSEQ*NBATCH*256];     /* hx per step (output GEMM input)   */
__device__ float g_hseqT[2][256*NBATCH];      /* transposed hx, parity-buffered    */
__device__ float g_cx  [NBATCH*256];          /* cell state, thread-mapped         */
__device__ float g_predpart[2][8*NBATCH*2];   /* parity-buffered pred partials     */
__device__ float g_whhP[8*256*128];           /* W_hh pre-permuted [h][k][u*4+g]   */
__device__ float g_woP [8*64];                /* W_out cols 88/89 per (h,u,d)      */

typedef unsigned long long u64;

__device__ __forceinline__ u64 pack2(float lo, float hi){
    u64 r; asm("mov.b64 %0,{%1,%2};" : "=l"(r) : "f"(lo), "f"(hi)); return r;
}
__device__ __forceinline__ void unpack2(u64 v, float& lo, float& hi){
    asm("mov.b64 {%0,%1},%2;" : "=f"(lo), "=f"(hi) : "l"(v));
}
__device__ __forceinline__ u64 fma2(u64 a, u64 b, u64 c){
    u64 d; asm("fma.rn.f32x2 %0,%1,%2,%3;" : "=l"(d) : "l"(a), "l"(b), "l"(c)); return d;
}
__device__ __forceinline__ float sigmoidf_(float x){
    return __fdividef(1.0f, 1.0f + __expf(-x));
}

/* ================= Kernel 0: one-time weight permutation ================= */
__global__ void prep_kernel(const float* __restrict__ W_hh,
                            const float* __restrict__ W_out)
{
    int k = blockIdx.x;            /* 0..255 */
    int c = threadIdx.x;           /* 0..255 */
#pragma unroll
    for (int i = 0; i < 4; i++){
        int col = c + i*256;       /* W_hh col = g*256 + h*32 + u */
        int g = col >> 8, hu = col & 255;
        int h = hu >> 5, u = hu & 31;
        g_whhP[((size_t)h*256 + k)*128 + u*4 + g] = W_hh[k*1024 + col];
    }
    if (k < 8 && c < 64){
        int uu = c >> 1, d = c & 1;
        g_woP[k*64 + c] = W_out[((size_t)(k*32 + uu))*90 + 88 + d];
    }
}

/* ================= Kernel 1: per-(b,t) set encoder ================= */
__global__ void enc_kernel(const float* __restrict__ coords,
                           const float* __restrict__ W_e1, const float* __restrict__ b_e1,
                           const float* __restrict__ W_e2, const float* __restrict__ b_e2)
{
    int rl = threadIdx.x >> 6;
    int j  = threadIdx.x & 63;
    size_t r = (size_t)blockIdx.x * 4 + rl;

    __shared__ float pt[4][44];
    __shared__ float m [4][2][64];

    if (j < 44) pt[rl][j] = coords[r*88 + ((j>>1)<<2) + (j&1)];
    __syncthreads();

    float w0 = W_e1[j], w1 = W_e1[64+j], bb = b_e1[j];
    float s1 = 0.f, s2 = 0.f;
#pragma unroll
    for (int p = 0; p < 11; p++){
        float hh = fmaf(pt[rl][2*p+1], w1, fmaf(pt[rl][2*p], w0, bb));
        s1 += fmaxf(hh, 0.f);
    }
#pragma unroll
    for (int p = 11; p < 22; p++){
        float hh = fmaf(pt[rl][2*p+1], w1, fmaf(pt[rl][2*p], w0, bb));
        s2 += fmaxf(hh, 0.f);
    }
    m[rl][0][j] = s1 * (1.0f/11.0f);
    m[rl][1][j] = s2 * (1.0f/11.0f);
    __syncthreads();

    float o1 = b_e2[j], o2 = b_e2[j];
#pragma unroll
    for (int k = 0; k < 64; k++){
        float w = W_e2[k*64 + j];
        o1 = fmaf(m[rl][0][k], w, o1);
        o2 = fmaf(m[rl][1][k], w, o2);
    }
    g_enc[r*128 + j]      = o1;
    g_enc[r*128 + 64 + j] = o2;
}

/* ================= Kernel 2: Xpre GEMM =================
   Output layout: g_xpre[r][h8*128 + u_local*4 + g], u_local 0..31.    */
__global__ void __launch_bounds__(256) xpre_kernel(
    const float* __restrict__ coords, const float* __restrict__ W_ih,
    const float* __restrict__ b_ih,   const float* __restrict__ b_hh)
{
    extern __shared__ float smx[];
    float* a_s = smx;            /* 32*132 = 4224 */
    float* w_s = a_s + 4224;     /* 32*64  = 2048 */
    float* epi = w_s + 2048;     /* 128*65 = 8320 */

    int h  = blockIdx.x;                 /* h16: 16 tiles of 16 units */
    size_t m0 = (size_t)blockIdx.y * 128;
    int tid = threadIdx.x;
    int tb = tid & 31, tu = tid >> 5;

    u64 acc2[4][4];
#pragma unroll
    for (int bi=0;bi<4;bi++)
#pragma unroll
        for (int g=0;g<4;g++) acc2[bi][g] = 0ULL;

    for (int k0 = 0; k0 < 172; k0 += 32){
#pragma unroll
        for (int i = 0; i < 16; i++){
            int li  = tid + i*256;
            int kk  = li & 31, row = li >> 5;
            int k   = k0 + kk;
            float v = 0.f;
            size_t r = m0 + row;
            if (k < 44)       v = coords[r*88 + ((k>>1)<<2) + (k&1)];
            else if (k < 172) v = g_enc[r*128 + (k-44)];
            a_s[kk*132 + row] = v;
        }
#pragma unroll
        for (int i = 0; i < 8; i++){
            int li = tid + i*256;
            int c  = li & 63, kk = li >> 6;
            int k  = k0 + kk;
            float v = 0.f;
            if (k < 172){
                int col = ((c>>4)<<8) + (h<<4) + (c&15);
                v = W_ih[k*1024 + col];
            }
            w_s[kk*64 + c] = v;
        }
        __syncthreads();
#pragma unroll
        for (int kk = 0; kk < 32; kk++){
            float4 a = *(const float4*)&a_s[kk*132 + 4*tb];
            u64 ax = pack2(a.x,a.x), ay = pack2(a.y,a.y);
            u64 az = pack2(a.z,a.z), aw = pack2(a.w,a.w);
            int kw = kk*64 + (tu<<1);
#pragma unroll
            for (int g = 0; g < 4; g++){
                u64 w2 = *(const u64*)&w_s[kw + g*16];
                acc2[0][g] = fma2(ax, w2, acc2[0][g]);
                acc2[1][g] = fma2(ay, w2, acc2[1][g]);
                acc2[2][g] = fma2(az, w2, acc2[2][g]);
                acc2[3][g] = fma2(aw, w2, acc2[3][g]);
            }
        }
        __syncthreads();
    }

#pragma unroll
    for (int g = 0; g < 4; g++){
        int col0 = (g<<8) + (h<<4) + 2*tu;
        float b0 = b_ih[col0]   + b_hh[col0];
        float b1 = b_ih[col0+1] + b_hh[col0+1];
#pragma unroll
        for (int bi = 0; bi < 4; bi++){
            float lo, hi; unpack2(acc2[bi][g], lo, hi);
            epi[(4*tb+bi)*65 + g*16 + 2*tu]     = lo + b0;
            epi[(4*tb+bi)*65 + g*16 + 2*tu + 1] = hi + b1;
        }
    }
    __syncthreads();
#pragma unroll
    for (int i = 0; i < 8; i++){
        int li = tid + i*256;            /* 2048 = 128 rows x 16 units */
        int row = li >> 4, j = li & 15;
        size_t r = m0 + row;
        int colp = (h>>1)*128 + ((h&1)*16 + j)*4;
        float4 v = make_float4(epi[row*65 +      j], epi[row*65 + 16 + j],
                               epi[row*65 + 32 + j], epi[row*65 + 48 + j]);
        *(float4*)&g_xpre[r*1024 + colp] = v;
    }
}

/* ================= Kernel 3: one recurrent step =================
   grid (8,16), 512 threads; thread: 4 rows x 1 unit x 4 gates.
   W_hh copied straight from pre-permuted global (conflict-free STS),
   coords staged to SMEM by all threads. Plain per-step launches —
   stream order is the global barrier (race-free).                     */
#define PTS 45
#define RNN_SMEM_FLOATS (32768 + 256*64 + 64*PTS + 64 + 64 + 64 + 64)

__global__ void __launch_bounds__(512) rnn_step_kernel(
    const float* __restrict__ coords, const float* __restrict__ W_ih,
    const float* __restrict__ b_out,  const float* __restrict__ pitch, int t)
{
    extern __shared__ float sm[];
    float* w_s   = sm;                     /* [256][128] c=u*4+g : 32768 f */
    float* hx_s  = w_s + 32768;            /* [256][64]          : 16384 f */
    float* epi   = hx_s;                   /* overlay, [row*33+u]          */
    float* pt_s  = hx_s + 16384;           /* [64][PTS]          : 2880 f  */
    float* wo_s  = pt_s + 64*PTS;          /* [32][2] */
    float* clo_s = wo_s + 64;
    float* px_s  = clo_s + 64;
    float* py_s  = px_s + 64;

    int h = blockIdx.x, bm = blockIdx.y;
    int tid = threadIdx.x;
    int u  = tid >> 4;                     /* unit 0..31      */
    int rb = tid & 15;                     /* row-block (x4)  */

    /* ---- W_hh slice: straight coalesced copy (conflict-free) ---- */
    {
        const float* wsrc = g_whhP + (size_t)h*256*128;
#pragma unroll
        for (int i = 0; i < 16; i++){
            int li = tid + i*512;          /* 8192 f4 */
            *(float4*)&w_s[li*4] = __ldcg((const float4*)&wsrc[li*4]);
        }
    }
    if (tid < 64) wo_s[tid] = g_woP[h*64 + tid];

    float cw[3][4];
#pragma unroll
    for (int j = 0; j < 3; j++)
#pragma unroll
        for (int g = 0; g < 4; g++)
            cw[j][g] = W_ih[(172+j)*1024 + g*256 + h*32 + u];

    float ps0 = pitch[0], ps1 = pitch[1];
    float bo88 = b_out[88], bo89 = b_out[89];

    /* xpre tile -> registers */
    float4 xv[4];
#pragma unroll
    for (int r = 0; r < 4; r++){
        size_t rglob = ((size_t)(bm*64 + rb*4 + r))*NSEQ + t;
        xv[r] = __ldcg((const float4*)&g_xpre[rglob*1024 + h*128 + u*4]);
    }

    /* coords (player xy) -> smem, stride PTS=45 */
    {
        int row = tid >> 3, j0 = tid & 7;
        size_t cbase = ((size_t)(bm*64 + row))*NSEQ + t;
        const float* cp = coords + cbase*88;
#pragma unroll
        for (int i = 0; i < 6; i++){
            int j = j0 + i*8;              /* 0..47 */
            if (j < 44)
                pt_s[row*PTS + j] = __ldg(&cp[((j>>1)<<2) + (j&1)]);
        }
    }
    __syncthreads();                       /* pt_s ready */

    /* ---- pred + closest distance (per batch row) ---- */
    if (tid < 64){
        int bg = bm*64 + tid;
        float px = 0.f, py = 0.f;
        if (t > 0){
            const float* pp = g_predpart[(t-1)&1];
#pragma unroll
            for (int hh = 0; hh < 8; hh++){
                float2 v = __ldcg((const float2*)&pp[((size_t)hh*NBATCH + bg)*2]);
                px += v.x; py += v.y;
            }
            px = (px + bo88) * ps0;
            py = (py + bo89) * ps1;
        }
        float md = 3.402823e38f;
#pragma unroll
        for (int p = 0; p < 22; p++){
            float dx = px - pt_s[tid*PTS + 2*p], dy = py - pt_s[tid*PTS + 2*p + 1];
            md = fminf(md, fmaf(dx,dx,dy*dy));
        }
        clo_s[tid] = sqrtf(md);
        px_s[tid] = px; py_s[tid] = py;
    }

    u64 acc[2][4];
#pragma unroll
    for (int rp=0;rp<2;rp++)
#pragma unroll
        for (int g=0;g<4;g++) acc[rp][g] = 0ULL;

    if (t > 0){
        /* ---- stage hx (all K) from transposed buffer, coalesced ---- */
        const float* hT = g_hseqT[(t-1)&1] + bm*64;
#pragma unroll
        for (int i = 0; i < 16; i++){
            int li = tid + i*512;          /* 8192 f2 = 256 k x 32 pairs */
            int k = li >> 5, l = li & 31;
            float2 v = __ldcg((const float2*)&hT[k*1024 + 2*l]);
            *(float2*)&hx_s[k*64 + 2*l] = v;
        }
        __syncthreads();

        /* ---- GEMM: 256 kk ---- */
        const float* hbase = hx_s + rb*4;
        const float* wbase = w_s + u*4;
#pragma unroll 8
        for (int kk = 0; kk < 256; kk++){
            ulonglong2 A = *(const ulonglong2*)(hbase + kk*64);
            float4 wv = *(const float4*)(wbase + kk*128);
            u64 w0 = pack2(wv.x, wv.x), w1 = pack2(wv.y, wv.y);
            u64 w2 = pack2(wv.z, wv.z), w3 = pack2(wv.w, wv.w);
            acc[0][0] = fma2(A.x, w0, acc[0][0]);
            acc[0][1] = fma2(A.x, w1, acc[0][1]);
            acc[0][2] = fma2(A.x, w2, acc[0][2]);
            acc[0][3] = fma2(A.x, w3, acc[0][3]);
            acc[1][0] = fma2(A.y, w0, acc[1][0]);
            acc[1][1] = fma2(A.y, w1, acc[1][1]);
            acc[1][2] = fma2(A.y, w2, acc[1][2]);
            acc[1][3] = fma2(A.y, w3, acc[1][3]);
        }
    }
    __syncthreads();   /* hx_s reads done -> epi overlay is safe */

    /* ---- LSTM pointwise; cx streamed via thread-mapped global ---- */
    {
        size_t cxbase = ((size_t)((h*16 + bm)*512 + tid))*4;
        float cx[4];
        if (t > 0){
            float4 c0 = __ldcg((const float4*)&g_cx[cxbase]);
            cx[0]=c0.x; cx[1]=c0.y; cx[2]=c0.z; cx[3]=c0.w;
        } else {
#pragma unroll
            for (int r = 0; r < 4; r++) cx[r] = 0.f;
        }
#pragma unroll
        for (int r = 0; r < 4; r++){
            int row = rb*4 + r;
            float clo = clo_s[row], ppx = px_s[row], ppy = py_s[row];
            float lo0, hi0, lo1, hi1, lo2, hi2, lo3, hi3;
            unpack2(acc[r>>1][0], lo0, hi0);
            unpack2(acc[r>>1][1], lo1, hi1);
            unpack2(acc[r>>1][2], lo2, hi2);
            unpack2(acc[r>>1][3], lo3, hi3);
            float gi = (r&1) ? hi0 : lo0;
            float gf = (r&1) ? hi1 : lo1;
            float gg = (r&1) ? hi2 : lo2;
            float go = (r&1) ? hi3 : lo3;
            gi += xv[r].x + clo*cw[0][0] + ppx*cw[1][0] + ppy*cw[2][0];
            gf += xv[r].y + clo*cw[0][1] + ppx*cw[1][1] + ppy*cw[2][1];
            gg += xv[r].z + clo*cw[0][2] + ppx*cw[1][2] + ppy*cw[2][2];
            go += xv[r].w + clo*cw[0][3] + ppx*cw[1][3] + ppy*cw[2][3];
            float c2 = sigmoidf_(gf)*cx[r] + sigmoidf_(gi)*tanhf(gg);
            float h2 = sigmoidf_(go)*tanhf(c2);
            cx[r] = c2;
            epi[row*33 + u] = h2;
        }
        *(float4*)&g_cx[cxbase] = make_float4(cx[0],cx[1],cx[2],cx[3]);
    }
    __syncthreads();

    /* ---- plain hseq store [t][b][256] ---- */
    {
        float* hout = g_hseq + ((size_t)t*NBATCH + bm*64)*256 + h*32;
#pragma unroll
        for (int i = 0; i < 4; i++){
            int li = tid + i*512;          /* 2048 = 64 rows x 32 c */
            int row = li >> 5, c = li & 31;
            hout[row*256 + c] = epi[row*33 + c];
        }
    }
    /* ---- transposed hseqT store [t&1][col][1024] ---- */
    {
        float* hT2 = g_hseqT[t&1] + bm*64;
#pragma unroll
        for (int i = 0; i < 4; i++){
            int li = tid + i*512;          /* 2048 = 32 cols x 64 rows */
            int col = li >> 6, row = li & 63;
            hT2[(size_t)(h*32 + col)*1024 + row] = epi[row*33 + col];
        }
    }
    /* ---- pred partials for step t+1 ---- */
    if (tid < 64){
        int bg = bm*64 + tid;
        float px = 0.f, py = 0.f;
#pragma unroll
        for (int uu = 0; uu < 32; uu++){
            float hv = epi[tid*33 + uu];
            px = fmaf(hv, wo_s[2*uu],   px);
            py = fmaf(hv, wo_s[2*uu+1], py);
        }
        *(float2*)&g_predpart[t&1][((size_t)h*NBATCH + bg)*2] = make_float2(px, py);
    }
}

/* ================= Kernel 4: output head GEMM ================= */
__global__ void __launch_bounds__(256) out_kernel(
    const float* __restrict__ W_out, const float* __restrict__ b_out,
    const float* __restrict__ pitch, float* __restrict__ out)
{
    size_t r0 = (size_t)blockIdx.x * 64;
    int tid = threadIdx.x;
    int tx = tid & 15, ty = tid >> 4;

    __shared__ float a_s[32*68];
    __shared__ float w_s[32*96];

    float acc[4][6];
#pragma unroll
    for (int bi=0;bi<4;bi++)
#pragma unroll
        for (int ci=0;ci<6;ci++) acc[bi][ci]=0.f;

    for (int k0 = 0; k0 < 256; k0 += 32){
#pragma unroll
        for (int i = 0; i < 8; i++){
            int li = tid + i*256;
            int kk = li & 31, row = li >> 5;
            size_t r = r0 + row;
            int t = (int)(r % NSEQ), b = (int)(r / NSEQ);
            a_s[kk*68 + row] = g_hseq[((size_t)t*NBATCH + b)*256 + k0 + kk];
        }
#pragma unroll
        for (int i = 0; i < 12; i++){
            int li = tid + i*256;
            int n = li % 96, kk = li / 96;
            w_s[kk*96 + n] = (n < 90) ? W_out[(k0+kk)*90 + n] : 0.f;
        }
        __syncthreads();
#pragma unroll
        for (int kk = 0; kk < 32; kk++){
            float4 a = *(const float4*)&a_s[kk*68 + 4*ty];
            float w[6];
#pragma unroll
            for (int ci = 0; ci < 6; ci++) w[ci] = w_s[kk*96 + 6*tx + ci];
#pragma unroll
            for (int ci = 0; ci < 6; ci++){
                acc[0][ci] = fmaf(a.x, w[ci], acc[0][ci]);
                acc[1][ci] = fmaf(a.y, w[ci], acc[1][ci]);
                acc[2][ci] = fmaf(a.z, w[ci], acc[2][ci]);
                acc[3][ci] = fmaf(a.w, w[ci], acc[3][ci]);
            }
        }
        __syncthreads();
    }
#pragma unroll
    for (int bi = 0; bi < 4; bi++){
        size_t r = r0 + 4*ty + bi;
#pragma unroll
        for (int ci = 0; ci < 6; ci++){
            int n = 6*tx + ci;
            if (n < 90)
                out[r*90 + n] = (acc[bi][ci] + b_out[n]) * pitch[n & 1];
        }
    }
}

/* ================= host launcher ================= */
extern "C" void kernel_launch(void* const* d_in, const int* in_sizes, int n_in,
                              void* d_out, int out_size)
{
    const float* coords = (const float*)d_in[0];
    const float* pitch  = (const float*)d_in[1];
    const float* W_e1   = (const float*)d_in[2];
    const float* b_e1   = (const float*)d_in[3];
    const float* W_e2   = (const float*)d_in[4];
    const float* b_e2   = (const float*)d_in[5];
    const float* W_ih   = (const float*)d_in[6];
    const float* b_ih   = (const float*)d_in[7];
    const float* W_hh   = (const float*)d_in[8];
    const float* b_hh   = (const float*)d_in[9];
    const float* W_out  = (const float*)d_in[10];
    const float* b_out  = (const float*)d_in[11];
    float* out = (float*)d_out;

    size_t xpre_smem = 14592u * sizeof(float);                  /*  58,368 B */
    size_t rnn_smem  = (size_t)RNN_SMEM_FLOATS * sizeof(float); /* ~209 KB  */
    static int attr_done = 0;
    if (!attr_done){
        cudaFuncSetAttribute(xpre_kernel, cudaFuncAttributeMaxDynamicSharedMemorySize,
                             (int)xpre_smem);
        cudaFuncSetAttribute(rnn_step_kernel, cudaFuncAttributeMaxDynamicSharedMemorySize,
                             (int)rnn_smem);
        attr_done = 1;
    }

    prep_kernel<<<256, 256>>>(W_hh, W_out);
    enc_kernel<<<NROWS/4, 256>>>(coords, W_e1, b_e1, W_e2, b_e2);
    xpre_kernel<<<dim3(16, NROWS/128), 256, xpre_smem>>>(coords, W_ih, b_ih, b_hh);

    for (int t = 0; t < NSEQ; t++)
        rnn_step_kernel<<<dim3(8,16), 512, rnn_smem>>>(coords, W_ih, b_out, pitch, t);

    out_kernel<<<NROWS/64, 256>>>(W_out, b_out, pitch, out);
}

// round 15
// speedup vs baseline: 1.3461x; 1.0023x over previous
#include <cuda_runtime.h>
#include <math.h>

#define NBATCH 1024
#define NSEQ   200
#define NROWS  (NBATCH*NSEQ)   /* 204800 */

/* ------------ static scratch (no allocations allowed) ------------ */
__device__ float g_enc [NROWS*128];           /* encoder output                    */
__device__ float g_xpre[NROWS*1024];          /* gate preacts, [r][h8*128 + u*4+g] */
__device__ float g_hseq[NSEQ*NBATCH*256];     /* hx per step (output GEMM input)   */
__device__ float g_hseqT[2][256*NBATCH];      /* transposed hx, parity-buffered    */
__device__ float g_cx  [NBATCH*256];          /* cell state, thread-mapped         */
__device__ float g_predpart[2][8*NBATCH*2];   /* parity-buffered pred partials     */
__device__ float g_whhP[8*256*128];           /* W_hh pre-permuted [h][k][u*4+g]   */
__device__ float g_woP [8*64];                /* W_out cols 88/89 per (h,u,d)      */

typedef unsigned long long u64;

__device__ __forceinline__ u64 pack2(float lo, float hi){
    u64 r; asm("mov.b64 %0,{%1,%2};" : "=l"(r) : "f"(lo), "f"(hi)); return r;
}
__device__ __forceinline__ void unpack2(u64 v, float& lo, float& hi){
    asm("mov.b64 {%0,%1},%2;" : "=f"(lo), "=f"(hi) : "l"(v));
}
__device__ __forceinline__ u64 fma2(u64 a, u64 b, u64 c){
    u64 d; asm("fma.rn.f32x2 %0,%1,%2,%3;" : "=l"(d) : "l"(a), "l"(b), "l"(c)); return d;
}
__device__ __forceinline__ float sigmoidf_(float x){
    return __fdividef(1.0f, 1.0f + __expf(-x));
}
__device__ __forceinline__ unsigned smem_u32(const void* p){
    unsigned a;
    asm("{ .reg .u64 t; cvta.to.shared.u64 t, %1; cvt.u32.u64 %0, t; }"
        : "=r"(a) : "l"(p));
    return a;
}
__device__ __forceinline__ void cpa16(unsigned dst, const void* src){
    asm volatile("cp.async.cg.shared.global [%0],[%1],16;" :: "r"(dst), "l"(src));
}
__device__ __forceinline__ void cpa_commit(){
    asm volatile("cp.async.commit_group;" ::: "memory");
}
template<int N>
__device__ __forceinline__ void cpa_wait(){
    asm volatile("cp.async.wait_group %0;" :: "n"(N) : "memory");
}

/* ================= Kernel 0: one-time weight permutation ================= */
__global__ void prep_kernel(const float* __restrict__ W_hh,
                            const float* __restrict__ W_out)
{
    int k = blockIdx.x;            /* 0..255 */
    int c = threadIdx.x;           /* 0..255 */
#pragma unroll
    for (int i = 0; i < 4; i++){
        int col = c + i*256;       /* W_hh col = g*256 + h*32 + u */
        int g = col >> 8, hu = col & 255;
        int h = hu >> 5, u = hu & 31;
        g_whhP[((size_t)h*256 + k)*128 + u*4 + g] = W_hh[k*1024 + col];
    }
    if (k < 8 && c < 64){
        int uu = c >> 1, d = c & 1;
        g_woP[k*64 + c] = W_out[((size_t)(k*32 + uu))*90 + 88 + d];
    }
}

/* ================= Kernel 1: per-(b,t) set encoder (weights in SMEM) ===== */
__global__ void enc_kernel(const float* __restrict__ coords,
                           const float* __restrict__ W_e1, const float* __restrict__ b_e1,
                           const float* __restrict__ W_e2, const float* __restrict__ b_e2)
{
    int rl = threadIdx.x >> 6;
    int j  = threadIdx.x & 63;
    int tid = threadIdx.x;
    size_t r = (size_t)blockIdx.x * 4 + rl;

    __shared__ float pt[4][44];
    __shared__ float m [4][2][64];
    __shared__ float we1[128], be1s[64], be2s[64];
    __shared__ float we2[4096];

    if (tid < 128) we1[tid] = W_e1[tid];
    if (tid < 64){ be1s[tid] = b_e1[tid]; be2s[tid] = b_e2[tid]; }
#pragma unroll
    for (int i = 0; i < 16; i++) we2[tid + i*256] = W_e2[tid + i*256];

    if (j < 44) pt[rl][j] = coords[r*88 + ((j>>1)<<2) + (j&1)];
    __syncthreads();

    float w0 = we1[j], w1 = we1[64+j], bb = be1s[j];
    float s1 = 0.f, s2 = 0.f;
#pragma unroll
    for (int p = 0; p < 11; p++){
        float hh = fmaf(pt[rl][2*p+1], w1, fmaf(pt[rl][2*p], w0, bb));
        s1 += fmaxf(hh, 0.f);
    }
#pragma unroll
    for (int p = 11; p < 22; p++){
        float hh = fmaf(pt[rl][2*p+1], w1, fmaf(pt[rl][2*p], w0, bb));
        s2 += fmaxf(hh, 0.f);
    }
    m[rl][0][j] = s1 * (1.0f/11.0f);
    m[rl][1][j] = s2 * (1.0f/11.0f);
    __syncthreads();

    float o1 = be2s[j], o2 = be2s[j];
#pragma unroll
    for (int k = 0; k < 64; k++){
        float w = we2[k*64 + j];
        o1 = fmaf(m[rl][0][k], w, o1);
        o2 = fmaf(m[rl][1][k], w, o2);
    }
    g_enc[r*128 + j]      = o1;
    g_enc[r*128 + 64 + j] = o2;
}

/* ================= Kernel 2: Xpre GEMM ================= */
__global__ void __launch_bounds__(256) xpre_kernel(
    const float* __restrict__ coords, const float* __restrict__ W_ih,
    const float* __restrict__ b_ih,   const float* __restrict__ b_hh)
{
    extern __shared__ float smx[];
    float* a_s = smx;            /* 32*132 = 4224 */
    float* w_s = a_s + 4224;     /* 32*64  = 2048 */
    float* epi = w_s + 2048;     /* 128*65 = 8320 */

    int h  = blockIdx.x;
    size_t m0 = (size_t)blockIdx.y * 128;
    int tid = threadIdx.x;
    int tb = tid & 31, tu = tid >> 5;

    u64 acc2[4][4];
#pragma unroll
    for (int bi=0;bi<4;bi++)
#pragma unroll
        for (int g=0;g<4;g++) acc2[bi][g] = 0ULL;

    for (int k0 = 0; k0 < 172; k0 += 32){
#pragma unroll
        for (int i = 0; i < 16; i++){
            int li  = tid + i*256;
            int kk  = li & 31, row = li >> 5;
            int k   = k0 + kk;
            float v = 0.f;
            size_t r = m0 + row;
            if (k < 44)       v = coords[r*88 + ((k>>1)<<2) + (k&1)];
            else if (k < 172) v = g_enc[r*128 + (k-44)];
            a_s[kk*132 + row] = v;
        }
#pragma unroll
        for (int i = 0; i < 8; i++){
            int li = tid + i*256;
            int c  = li & 63, kk = li >> 6;
            int k  = k0 + kk;
            float v = 0.f;
            if (k < 172){
                int col = ((c>>4)<<8) + (h<<4) + (c&15);
                v = W_ih[k*1024 + col];
            }
            w_s[kk*64 + c] = v;
        }
        __syncthreads();
#pragma unroll
        for (int kk = 0; kk < 32; kk++){
            float4 a = *(const float4*)&a_s[kk*132 + 4*tb];
            u64 ax = pack2(a.x,a.x), ay = pack2(a.y,a.y);
            u64 az = pack2(a.z,a.z), aw = pack2(a.w,a.w);
            int kw = kk*64 + (tu<<1);
#pragma unroll
            for (int g = 0; g < 4; g++){
                u64 w2 = *(const u64*)&w_s[kw + g*16];
                acc2[0][g] = fma2(ax, w2, acc2[0][g]);
                acc2[1][g] = fma2(ay, w2, acc2[1][g]);
                acc2[2][g] = fma2(az, w2, acc2[2][g]);
                acc2[3][g] = fma2(aw, w2, acc2[3][g]);
            }
        }
        __syncthreads();
    }

#pragma unroll
    for (int g = 0; g < 4; g++){
        int col0 = (g<<8) + (h<<4) + 2*tu;
        float b0 = b_ih[col0]   + b_hh[col0];
        float b1 = b_ih[col0+1] + b_hh[col0+1];
#pragma unroll
        for (int bi = 0; bi < 4; bi++){
            float lo, hi; unpack2(acc2[bi][g], lo, hi);
            epi[(4*tb+bi)*65 + g*16 + 2*tu]     = lo + b0;
            epi[(4*tb+bi)*65 + g*16 + 2*tu + 1] = hi + b1;
        }
    }
    __syncthreads();
#pragma unroll
    for (int i = 0; i < 8; i++){
        int li = tid + i*256;
        int row = li >> 4, j = li & 15;
        size_t r = m0 + row;
        int colp = (h>>1)*128 + ((h&1)*16 + j)*4;
        float4 v = make_float4(epi[row*65 +      j], epi[row*65 + 16 + j],
                               epi[row*65 + 32 + j], epi[row*65 + 48 + j]);
        *(float4*)&g_xpre[r*1024 + colp] = v;
    }
}

/* ================= Kernel 3: one recurrent step (cp.async pipelined) =====
   grid (8,16), 512 threads; thread: 4 rows x 1 unit x 4 gates.
   K=256 split into 4 chunks of 64; W-chunk (32KB) and hx-chunk (16KB)
   double-buffered via cp.async so staging hides behind the FMA loop.  */
#define PTS 45
#define WB_CH 8192              /* 64 kk x 128 cols */
#define HB_CH 4096              /* 64 kk x 64 rows  */
#define RNN_SMEM_FLOATS (2*WB_CH + 2*HB_CH + 64*PTS + 64 + 64 + 64 + 64)

__global__ void __launch_bounds__(512) rnn_step_kernel(
    const float* __restrict__ coords, const float* __restrict__ W_ih,
    const float* __restrict__ b_out,  const float* __restrict__ pitch, int t)
{
    extern __shared__ float sm[];
    float* wb    = sm;                     /* [2][WB_CH] */
    float* hb    = wb + 2*WB_CH;           /* [2][HB_CH] */
    float* epi   = sm;                     /* overlay on wb[0], [row*33+u] */
    float* pt_s  = hb + 2*HB_CH;           /* [64][PTS] */
    float* wo_s  = pt_s + 64*PTS;
    float* clo_s = wo_s + 64;
    float* px_s  = clo_s + 64;
    float* py_s  = px_s + 64;

    int h = blockIdx.x, bm = blockIdx.y;
    int tid = threadIdx.x;
    int u  = tid >> 4;                     /* unit 0..31      */
    int rb = tid & 15;                     /* row-block (x4)  */

    const float* wsrc = g_whhP + (size_t)h*256*128;
    const float* hT   = g_hseqT[(t-1)&1] + bm*64;
    unsigned wb_a = smem_u32(wb), hb_a = smem_u32(hb);

    /* ---- kick off chunk 0 (t>0) before doing the front ---- */
    if (t > 0){
#pragma unroll
        for (int i = 0; i < 4; i++){
            int li = tid + i*512;          /* 2048 f4 = chunk W */
            cpa16(wb_a + li*16, wsrc + li*4);
        }
#pragma unroll
        for (int i = 0; i < 2; i++){
            int li = tid + i*512;          /* 1024 f4 = chunk hx */
            int k = li >> 4, c4 = li & 15;
            cpa16(hb_a + (k*64 + c4*4)*4, hT + (size_t)k*1024 + c4*4);
        }
        cpa_commit();
    }

    /* ---- FRONT (overlaps cp.async) ---- */
    if (tid < 64) wo_s[tid] = g_woP[h*64 + tid];

    float cw[3][4];
#pragma unroll
    for (int j = 0; j < 3; j++)
#pragma unroll
        for (int g = 0; g < 4; g++)
            cw[j][g] = W_ih[(172+j)*1024 + g*256 + h*32 + u];

    float ps0 = pitch[0], ps1 = pitch[1];
    float bo88 = b_out[88], bo89 = b_out[89];

    float4 xv[4];
#pragma unroll
    for (int r = 0; r < 4; r++){
        size_t rglob = ((size_t)(bm*64 + rb*4 + r))*NSEQ + t;
        xv[r] = __ldcg((const float4*)&g_xpre[rglob*1024 + h*128 + u*4]);
    }

    {
        int row = tid >> 3, j0 = tid & 7;
        size_t cbase = ((size_t)(bm*64 + row))*NSEQ + t;
        const float* cp = coords + cbase*88;
#pragma unroll
        for (int i = 0; i < 6; i++){
            int j = j0 + i*8;
            if (j < 44)
                pt_s[row*PTS + j] = __ldg(&cp[((j>>1)<<2) + (j&1)]);
        }
    }
    __syncthreads();                       /* pt_s ready */

    /* ---- pred + closest distance (per batch row) ---- */
    if (tid < 64){
        int bg = bm*64 + tid;
        float px = 0.f, py = 0.f;
        if (t > 0){
            const float* pp = g_predpart[(t-1)&1];
#pragma unroll
            for (int hh = 0; hh < 8; hh++){
                float2 v = __ldcg((const float2*)&pp[((size_t)hh*NBATCH + bg)*2]);
                px += v.x; py += v.y;
            }
            px = (px + bo88) * ps0;
            py = (py + bo89) * ps1;
        }
        float md = 3.402823e38f;
#pragma unroll
        for (int p = 0; p < 22; p++){
            float dx = px - pt_s[tid*PTS + 2*p], dy = py - pt_s[tid*PTS + 2*p + 1];
            md = fminf(md, fmaf(dx,dx,dy*dy));
        }
        clo_s[tid] = sqrtf(md);
        px_s[tid] = px; py_s[tid] = py;
    }

    u64 acc[2][4];
#pragma unroll
    for (int rp=0;rp<2;rp++)
#pragma unroll
        for (int g=0;g<4;g++) acc[rp][g] = 0ULL;

    if (t > 0){
        /* ---- pipelined GEMM over 4 chunks of 64 kk ---- */
        for (int c = 0; c < 4; c++){
            if (c < 3){
                int buf = (c+1)&1;
#pragma unroll
                for (int i = 0; i < 4; i++){
                    int li = tid + i*512;
                    cpa16(wb_a + (buf*WB_CH + li*4)*4,
                          wsrc + (size_t)(c+1)*WB_CH + li*4);
                }
#pragma unroll
                for (int i = 0; i < 2; i++){
                    int li = tid + i*512;
                    int k = li >> 4, c4 = li & 15;
                    cpa16(hb_a + (buf*HB_CH + k*64 + c4*4)*4,
                          hT + (size_t)((c+1)*64 + k)*1024 + c4*4);
                }
                cpa_commit();
                cpa_wait<1>();
            } else {
                cpa_wait<0>();
            }
            __syncthreads();               /* chunk c data visible to all */

            const float* hbase = hb + (c&1)*HB_CH + rb*4;
            const float* wbase = wb + (c&1)*WB_CH + u*4;
#pragma unroll 8
            for (int kk = 0; kk < 64; kk++){
                ulonglong2 A = *(const ulonglong2*)(hbase + kk*64);
                float4 wv = *(const float4*)(wbase + kk*128);
                u64 w0 = pack2(wv.x, wv.x), w1 = pack2(wv.y, wv.y);
                u64 w2 = pack2(wv.z, wv.z), w3 = pack2(wv.w, wv.w);
                acc[0][0] = fma2(A.x, w0, acc[0][0]);
                acc[0][1] = fma2(A.x, w1, acc[0][1]);
                acc[0][2] = fma2(A.x, w2, acc[0][2]);
                acc[0][3] = fma2(A.x, w3, acc[0][3]);
                acc[1][0] = fma2(A.y, w0, acc[1][0]);
                acc[1][1] = fma2(A.y, w1, acc[1][1]);
                acc[1][2] = fma2(A.y, w2, acc[1][2]);
                acc[1][3] = fma2(A.y, w3, acc[1][3]);
            }
            __syncthreads();               /* buf reads done before re-fill */
        }
    } else {
        __syncthreads();                   /* clo_s ready for pointwise */
    }

    /* ---- LSTM pointwise; cx streamed via thread-mapped global ---- */
    {
        size_t cxbase = ((size_t)((h*16 + bm)*512 + tid))*4;
        float cx[4];
        if (t > 0){
            float4 c0 = __ldcg((const float4*)&g_cx[cxbase]);
            cx[0]=c0.x; cx[1]=c0.y; cx[2]=c0.z; cx[3]=c0.w;
        } else {
#pragma unroll
            for (int r = 0; r < 4; r++) cx[r] = 0.f;
        }
#pragma unroll
        for (int r = 0; r < 4; r++){
            int row = rb*4 + r;
            float clo = clo_s[row], ppx = px_s[row], ppy = py_s[row];
            float lo0, hi0, lo1, hi1, lo2, hi2, lo3, hi3;
            unpack2(acc[r>>1][0], lo0, hi0);
            unpack2(acc[r>>1][1], lo1, hi1);
            unpack2(acc[r>>1][2], lo2, hi2);
            unpack2(acc[r>>1][3], lo3, hi3);
            float gi = (r&1) ? hi0 : lo0;
            float gf = (r&1) ? hi1 : lo1;
            float gg = (r&1) ? hi2 : lo2;
            float go = (r&1) ? hi3 : lo3;
            gi += xv[r].x + clo*cw[0][0] + ppx*cw[1][0] + ppy*cw[2][0];
            gf += xv[r].y + clo*cw[0][1] + ppx*cw[1][1] + ppy*cw[2][1];
            gg += xv[r].z + clo*cw[0][2] + ppx*cw[1][2] + ppy*cw[2][2];
            go += xv[r].w + clo*cw[0][3] + ppx*cw[1][3] + ppy*cw[2][3];
            float c2 = sigmoidf_(gf)*cx[r] + sigmoidf_(gi)*tanhf(gg);
            float h2 = sigmoidf_(go)*tanhf(c2);
            cx[r] = c2;
            epi[row*33 + u] = h2;
        }
        *(float4*)&g_cx[cxbase] = make_float4(cx[0],cx[1],cx[2],cx[3]);
    }
    __syncthreads();

    /* ---- plain hseq store [t][b][256] ---- */
    {
        float* hout = g_hseq + ((size_t)t*NBATCH + bm*64)*256 + h*32;
#pragma unroll
        for (int i = 0; i < 4; i++){
            int li = tid + i*512;
            int row = li >> 5, c = li & 31;
            hout[row*256 + c] = epi[row*33 + c];
        }
    }
    /* ---- transposed hseqT store [t&1][col][1024] ---- */
    {
        float* hT2 = g_hseqT[t&1] + bm*64;
#pragma unroll
        for (int i = 0; i < 4; i++){
            int li = tid + i*512;
            int col = li >> 6, row = li & 63;
            hT2[(size_t)(h*32 + col)*1024 + row] = epi[row*33 + col];
        }
    }
    /* ---- pred partials for step t+1 ---- */
    if (tid < 64){
        int bg = bm*64 + tid;
        float px = 0.f, py = 0.f;
#pragma unroll
        for (int uu = 0; uu < 32; uu++){
            float hv = epi[tid*33 + uu];
            px = fmaf(hv, wo_s[2*uu],   px);
            py = fmaf(hv, wo_s[2*uu+1], py);
        }
        *(float2*)&g_predpart[t&1][((size_t)h*NBATCH + bg)*2] = make_float2(px, py);
    }
}

/* ================= Kernel 4: output head GEMM ================= */
__global__ void __launch_bounds__(256) out_kernel(
    const float* __restrict__ W_out, const float* __restrict__ b_out,
    const float* __restrict__ pitch, float* __restrict__ out)
{
    size_t r0 = (size_t)blockIdx.x * 64;
    int tid = threadIdx.x;
    int tx = tid & 15, ty = tid >> 4;

    __shared__ float a_s[32*68];
    __shared__ float w_s[32*96];

    float acc[4][6];
#pragma unroll
    for (int bi=0;bi<4;bi++)
#pragma unroll
        for (int ci=0;ci<6;ci++) acc[bi][ci]=0.f;

    for (int k0 = 0; k0 < 256; k0 += 32){
#pragma unroll
        for (int i = 0; i < 8; i++){
            int li = tid + i*256;
            int kk = li & 31, row = li >> 5;
            size_t r = r0 + row;
            int t = (int)(r % NSEQ), b = (int)(r / NSEQ);
            a_s[kk*68 + row] = g_hseq[((size_t)t*NBATCH + b)*256 + k0 + kk];
        }
#pragma unroll
        for (int i = 0; i < 12; i++){
            int li = tid + i*256;
            int n = li % 96, kk = li / 96;
            w_s[kk*96 + n] = (n < 90) ? W_out[(k0+kk)*90 + n] : 0.f;
        }
        __syncthreads();
#pragma unroll
        for (int kk = 0; kk < 32; kk++){
            float4 a = *(const float4*)&a_s[kk*68 + 4*ty];
            float w[6];
#pragma unroll
            for (int ci = 0; ci < 6; ci++) w[ci] = w_s[kk*96 + 6*tx + ci];
#pragma unroll
            for (int ci = 0; ci < 6; ci++){
                acc[0][ci] = fmaf(a.x, w[ci], acc[0][ci]);
                acc[1][ci] = fmaf(a.y, w[ci], acc[1][ci]);
                acc[2][ci] = fmaf(a.z, w[ci], acc[2][ci]);
                acc[3][ci] = fmaf(a.w, w[ci], acc[3][ci]);
            }
        }
        __syncthreads();
    }
#pragma unroll
    for (int bi = 0; bi < 4; bi++){
        size_t r = r0 + 4*ty + bi;
#pragma unroll
        for (int ci = 0; ci < 6; ci++){
            int n = 6*tx + ci;
            if (n < 90)
                out[r*90 + n] = (acc[bi][ci] + b_out[n]) * pitch[n & 1];
        }
    }
}

/* ================= host launcher ================= */
extern "C" void kernel_launch(void* const* d_in, const int* in_sizes, int n_in,
                              void* d_out, int out_size)
{
    const float* coords = (const float*)d_in[0];
    const float* pitch  = (const float*)d_in[1];
    const float* W_e1   = (const float*)d_in[2];
    const float* b_e1   = (const float*)d_in[3];
    const float* W_e2   = (const float*)d_in[4];
    const float* b_e2   = (const float*)d_in[5];
    const float* W_ih   = (const float*)d_in[6];
    const float* b_ih   = (const float*)d_in[7];
    const float* W_hh   = (const float*)d_in[8];
    const float* b_hh   = (const float*)d_in[9];
    const float* W_out  = (const float*)d_in[10];
    const float* b_out  = (const float*)d_in[11];
    float* out = (float*)d_out;

    size_t xpre_smem = 14592u * sizeof(float);                  /*  58,368 B */
    size_t rnn_smem  = (size_t)RNN_SMEM_FLOATS * sizeof(float); /* ~111 KB  */
    static int attr_done = 0;
    if (!attr_done){
        cudaFuncSetAttribute(xpre_kernel, cudaFuncAttributeMaxDynamicSharedMemorySize,
                             (int)xpre_smem);
        cudaFuncSetAttribute(rnn_step_kernel, cudaFuncAttributeMaxDynamicSharedMemorySize,
                             (int)rnn_smem);
        attr_done = 1;
    }

    prep_kernel<<<256, 256>>>(W_hh, W_out);
    enc_kernel<<<NROWS/4, 256>>>(coords, W_e1, b_e1, W_e2, b_e2);
    xpre_kernel<<<dim3(16, NROWS/128), 256, xpre_smem>>>(coords, W_ih, b_ih, b_hh);

    for (int t = 0; t < NSEQ; t++)
        rnn_step_kernel<<<dim3(8,16), 512, rnn_smem>>>(coords, W_ih, b_out, pitch, t);

    out_kernel<<<NROWS/64, 256>>>(W_out, b_out, pitch, out);
}

// round 16
// speedup vs baseline: 1.7379x; 1.2910x over previous
#include <cuda_runtime.h>
#include <math.h>

#define NBATCH 1024
#define NSEQ   200
#define NROWS  (NBATCH*NSEQ)   /* 204800 */
#define KPAD   192             /* xpre K padded (172 real + 20 zero) */

/* ------------ static scratch (no allocations allowed) ------------ */
__device__ float g_xaT [KPAD*NROWS];          /* A transposed [k][r], zero-padded  */
__device__ float g_xpre[NROWS*1024];          /* gate preacts, [r][h8*128 + u*4+g] */
__device__ float g_hseq[NSEQ*NBATCH*256];     /* hx per step (output GEMM input)   */
__device__ float g_hseqT[2][256*NBATCH];      /* transposed hx, parity-buffered    */
__device__ float g_cx  [NBATCH*256];          /* cell state, thread-mapped         */
__device__ float g_predpart[2][8*NBATCH*2];   /* parity-buffered pred partials     */
__device__ float g_whhP[8*256*128];           /* W_hh pre-permuted [h][k][u*4+g]   */
__device__ float g_wihP[8*KPAD*128];          /* W_ih rows 0..171 permuted, padded */
__device__ float g_biasP[8*128];              /* b_ih+b_hh permuted [h8][u*4+g]    */
__device__ float g_woP [8*64];                /* W_out cols 88/89 per (h,u,d)      */

typedef unsigned long long u64;

__device__ __forceinline__ u64 pack2(float lo, float hi){
    u64 r; asm("mov.b64 %0,{%1,%2};" : "=l"(r) : "f"(lo), "f"(hi)); return r;
}
__device__ __forceinline__ void unpack2(u64 v, float& lo, float& hi){
    asm("mov.b64 {%0,%1},%2;" : "=f"(lo), "=f"(hi) : "l"(v));
}
__device__ __forceinline__ u64 fma2(u64 a, u64 b, u64 c){
    u64 d; asm("fma.rn.f32x2 %0,%1,%2,%3;" : "=l"(d) : "l"(a), "l"(b), "l"(c)); return d;
}
__device__ __forceinline__ float sigmoidf_(float x){
    return __fdividef(1.0f, 1.0f + __expf(-x));
}
__device__ __forceinline__ unsigned smem_u32(const void* p){
    unsigned a;
    asm("{ .reg .u64 t; cvta.to.shared.u64 t, %1; cvt.u32.u64 %0, t; }"
        : "=r"(a) : "l"(p));
    return a;
}
__device__ __forceinline__ void cpa16(unsigned dst, const void* src){
    asm volatile("cp.async.cg.shared.global [%0],[%1],16;" :: "r"(dst), "l"(src));
}
__device__ __forceinline__ void cpa_commit(){
    asm volatile("cp.async.commit_group;" ::: "memory");
}
template<int N>
__device__ __forceinline__ void cpa_wait(){
    asm volatile("cp.async.wait_group %0;" :: "n"(N) : "memory");
}

/* ================= Kernel 0: one-time weight permutation ================= */
__global__ void prep_kernel(const float* __restrict__ W_hh,
                            const float* __restrict__ W_out,
                            const float* __restrict__ W_ih,
                            const float* __restrict__ b_ih,
                            const float* __restrict__ b_hh)
{
    int k = blockIdx.x;            /* 0..255 */
    int c = threadIdx.x;           /* 0..255 */
#pragma unroll
    for (int i = 0; i < 4; i++){
        int col = c + i*256;       /* col = g*256 + h*32 + u */
        int g = col >> 8, hu = col & 255;
        int h = hu >> 5, u = hu & 31;
        g_whhP[((size_t)h*256 + k)*128 + u*4 + g] = W_hh[k*1024 + col];
        if (k < KPAD)
            g_wihP[((size_t)h*KPAD + k)*128 + u*4 + g] =
                (k < 172) ? W_ih[k*1024 + col] : 0.f;
    }
    if (k < 4){
        int idx = k*256 + c;       /* 0..1023 */
        int h8 = idx >> 7, cc = idx & 127;
        int u = cc >> 2, g = cc & 3;
        int col = g*256 + h8*32 + u;
        g_biasP[idx] = b_ih[col] + b_hh[col];
    }
    if (k < 8 && c < 64){
        int uu = c >> 1, d = c & 1;
        g_woP[k*64 + c] = W_out[((size_t)(k*32 + uu))*90 + 88 + d];
    }
}

/* ================= Kernel 0b: coords transpose + zero pad rows ================= */
__global__ void tcoords_kernel(const float* __restrict__ coords)
{
    int tid = threadIdx.x;
    int r = blockIdx.x * 512 + tid;        /* 400*512 = 204800 */
    int y = blockIdx.y;                    /* 0..63 */
    int k = (y < 44) ? y : (128 + y);      /* 0..43 | 172..191 */
    float v = 0.f;
    if (y < 44)
        v = coords[(size_t)r*88 + ((y>>1)<<2) + (y&1)];
    g_xaT[(size_t)k*NROWS + r] = v;
}

/* ================= Kernel 1: per-(b,t) set encoder (writes transposed) ==== */
__global__ void enc_kernel(const float* __restrict__ coords,
                           const float* __restrict__ W_e1, const float* __restrict__ b_e1,
                           const float* __restrict__ W_e2, const float* __restrict__ b_e2)
{
    int rl = threadIdx.x >> 6;
    int j  = threadIdx.x & 63;
    int tid = threadIdx.x;
    size_t r = (size_t)blockIdx.x * 4 + rl;

    __shared__ float pt[4][44];
    __shared__ float m [4][2][64];
    __shared__ float we1[128], be1s[64], be2s[64];
    __shared__ float we2[4096];

    if (tid < 128) we1[tid] = W_e1[tid];
    if (tid < 64){ be1s[tid] = b_e1[tid]; be2s[tid] = b_e2[tid]; }
#pragma unroll
    for (int i = 0; i < 16; i++) we2[tid + i*256] = W_e2[tid + i*256];

    if (j < 44) pt[rl][j] = coords[r*88 + ((j>>1)<<2) + (j&1)];
    __syncthreads();

    float w0 = we1[j], w1 = we1[64+j], bb = be1s[j];
    float s1 = 0.f, s2 = 0.f;
#pragma unroll
    for (int p = 0; p < 11; p++){
        float hh = fmaf(pt[rl][2*p+1], w1, fmaf(pt[rl][2*p], w0, bb));
        s1 += fmaxf(hh, 0.f);
    }
#pragma unroll
    for (int p = 11; p < 22; p++){
        float hh = fmaf(pt[rl][2*p+1], w1, fmaf(pt[rl][2*p], w0, bb));
        s2 += fmaxf(hh, 0.f);
    }
    m[rl][0][j] = s1 * (1.0f/11.0f);
    m[rl][1][j] = s2 * (1.0f/11.0f);
    __syncthreads();

    float o1 = be2s[j], o2 = be2s[j];
#pragma unroll
    for (int k = 0; k < 64; k++){
        float w = we2[k*64 + j];
        o1 = fmaf(m[rl][0][k], w, o1);
        o2 = fmaf(m[rl][1][k], w, o2);
    }
    g_xaT[(size_t)(44 + j)*NROWS + r]  = o1;
    g_xaT[(size_t)(108 + j)*NROWS + r] = o2;
}

/* ================= Kernel 2: Xpre GEMM (rnn-GEMM clone) =================
   grid (8, 3200), 512 threads; thread: 4 rows x 1 unit x 4 gates.
   A from g_xaT (transposed, padded), W from g_wihP; 3 K-chunks of 64,
   double-buffered cp.async; conflict-free LDS.128; direct STG epilogue. */
#define XCH 64
#define XWB (XCH*128)   /* 8192 floats */
#define XAB (XCH*64)    /* 4096 floats */
#define XPRE_SMEM_FLOATS (2*XWB + 2*XAB)

__global__ void __launch_bounds__(512) xpre_kernel(void)
{
    extern __shared__ float sm[];
    float* wb = sm;                 /* [2][XWB] */
    float* ab = sm + 2*XWB;         /* [2][XAB] */

    int h8 = blockIdx.x;
    size_t r0 = (size_t)blockIdx.y * 64;
    int tid = threadIdx.x;
    int u  = tid >> 4;              /* unit 0..31     */
    int rb = tid & 15;              /* row-block (x4) */

    const float* wsrc = g_wihP + (size_t)h8*KPAD*128;
    unsigned wba = smem_u32(wb), aba = smem_u32(ab);

    /* chunk 0 */
#pragma unroll
    for (int i = 0; i < 4; i++){
        int li = tid + i*512;       /* 2048 f4 = 64k x 128c */
        cpa16(wba + li*16, wsrc + li*4);
    }
#pragma unroll
    for (int i = 0; i < 2; i++){
        int li = tid + i*512;       /* 1024 f4 = 64k x 16 f4 */
        int k = li >> 4, c4 = li & 15;
        cpa16(aba + (k*64 + c4*4)*4, g_xaT + (size_t)k*NROWS + r0 + c4*4);
    }
    cpa_commit();

    float4 bias = *(const float4*)&g_biasP[h8*128 + u*4];

    u64 acc[2][4];
#pragma unroll
    for (int rp=0;rp<2;rp++)
#pragma unroll
        for (int g=0;g<4;g++) acc[rp][g] = 0ULL;

    for (int c = 0; c < 3; c++){
        if (c < 2){
            int buf = (c+1)&1;
#pragma unroll
            for (int i = 0; i < 4; i++){
                int li = tid + i*512;
                cpa16(wba + (buf*XWB + li*4)*4, wsrc + (size_t)(c+1)*XWB + li*4);
            }
#pragma unroll
            for (int i = 0; i < 2; i++){
                int li = tid + i*512;
                int k = li >> 4, c4 = li & 15;
                cpa16(aba + (buf*XAB + k*64 + c4*4)*4,
                      g_xaT + (size_t)((c+1)*XCH + k)*NROWS + r0 + c4*4);
            }
            cpa_commit();
            cpa_wait<1>();
        } else {
            cpa_wait<0>();
        }
        __syncthreads();

        const float* hb_ = ab + (c&1)*XAB + rb*4;
        const float* wb_ = wb + (c&1)*XWB + u*4;
#pragma unroll 8
        for (int kk = 0; kk < XCH; kk++){
            ulonglong2 A = *(const ulonglong2*)(hb_ + kk*64);
            float4 wv = *(const float4*)(wb_ + kk*128);
            u64 w0 = pack2(wv.x, wv.x), w1 = pack2(wv.y, wv.y);
            u64 w2 = pack2(wv.z, wv.z), w3 = pack2(wv.w, wv.w);
            acc[0][0] = fma2(A.x, w0, acc[0][0]);
            acc[0][1] = fma2(A.x, w1, acc[0][1]);
            acc[0][2] = fma2(A.x, w2, acc[0][2]);
            acc[0][3] = fma2(A.x, w3, acc[0][3]);
            acc[1][0] = fma2(A.y, w0, acc[1][0]);
            acc[1][1] = fma2(A.y, w1, acc[1][1]);
            acc[1][2] = fma2(A.y, w2, acc[1][2]);
            acc[1][3] = fma2(A.y, w3, acc[1][3]);
        }
        __syncthreads();
    }

    /* epilogue: bias + direct coalesced-ish store */
#pragma unroll
    for (int rr = 0; rr < 4; rr++){
        size_t r = r0 + rb*4 + rr;
        float lo0, hi0, lo1, hi1, lo2, hi2, lo3, hi3;
        unpack2(acc[rr>>1][0], lo0, hi0);
        unpack2(acc[rr>>1][1], lo1, hi1);
        unpack2(acc[rr>>1][2], lo2, hi2);
        unpack2(acc[rr>>1][3], lo3, hi3);
        float4 o;
        o.x = ((rr&1) ? hi0 : lo0) + bias.x;
        o.y = ((rr&1) ? hi1 : lo1) + bias.y;
        o.z = ((rr&1) ? hi2 : lo2) + bias.z;
        o.w = ((rr&1) ? hi3 : lo3) + bias.w;
        *(float4*)&g_xpre[r*1024 + h8*128 + u*4] = o;
    }
}

/* ================= Kernel 3: one recurrent step (cp.async pipelined) ===== */
#define PTS 45
#define WB_CH 8192
#define HB_CH 4096
#define RNN_SMEM_FLOATS (2*WB_CH + 2*HB_CH + 64*PTS + 64 + 64 + 64 + 64)

__global__ void __launch_bounds__(512) rnn_step_kernel(
    const float* __restrict__ coords, const float* __restrict__ W_ih,
    const float* __restrict__ b_out,  const float* __restrict__ pitch, int t)
{
    extern __shared__ float sm[];
    float* wb    = sm;                     /* [2][WB_CH] */
    float* hb    = wb + 2*WB_CH;           /* [2][HB_CH] */
    float* epi   = sm;                     /* overlay on wb[0], [row*33+u] */
    float* pt_s  = hb + 2*HB_CH;           /* [64][PTS] */
    float* wo_s  = pt_s + 64*PTS;
    float* clo_s = wo_s + 64;
    float* px_s  = clo_s + 64;
    float* py_s  = px_s + 64;

    int h = blockIdx.x, bm = blockIdx.y;
    int tid = threadIdx.x;
    int u  = tid >> 4;
    int rb = tid & 15;

    const float* wsrc = g_whhP + (size_t)h*256*128;
    const float* hT   = g_hseqT[(t-1)&1] + bm*64;
    unsigned wb_a = smem_u32(wb), hb_a = smem_u32(hb);

    if (t > 0){
#pragma unroll
        for (int i = 0; i < 4; i++){
            int li = tid + i*512;
            cpa16(wb_a + li*16, wsrc + li*4);
        }
#pragma unroll
        for (int i = 0; i < 2; i++){
            int li = tid + i*512;
            int k = li >> 4, c4 = li & 15;
            cpa16(hb_a + (k*64 + c4*4)*4, hT + (size_t)k*1024 + c4*4);
        }
        cpa_commit();
    }

    if (tid < 64) wo_s[tid] = g_woP[h*64 + tid];

    float cw[3][4];
#pragma unroll
    for (int j = 0; j < 3; j++)
#pragma unroll
        for (int g = 0; g < 4; g++)
            cw[j][g] = W_ih[(172+j)*1024 + g*256 + h*32 + u];

    float ps0 = pitch[0], ps1 = pitch[1];
    float bo88 = b_out[88], bo89 = b_out[89];

    float4 xv[4];
#pragma unroll
    for (int r = 0; r < 4; r++){
        size_t rglob = ((size_t)(bm*64 + rb*4 + r))*NSEQ + t;
        xv[r] = __ldcg((const float4*)&g_xpre[rglob*1024 + h*128 + u*4]);
    }

    {
        int row = tid >> 3, j0 = tid & 7;
        size_t cbase = ((size_t)(bm*64 + row))*NSEQ + t;
        const float* cp = coords + cbase*88;
#pragma unroll
        for (int i = 0; i < 6; i++){
            int j = j0 + i*8;
            if (j < 44)
                pt_s[row*PTS + j] = __ldg(&cp[((j>>1)<<2) + (j&1)]);
        }
    }
    __syncthreads();

    if (tid < 64){
        int bg = bm*64 + tid;
        float px = 0.f, py = 0.f;
        if (t > 0){
            const float* pp = g_predpart[(t-1)&1];
#pragma unroll
            for (int hh = 0; hh < 8; hh++){
                float2 v = __ldcg((const float2*)&pp[((size_t)hh*NBATCH + bg)*2]);
                px += v.x; py += v.y;
            }
            px = (px + bo88) * ps0;
            py = (py + bo89) * ps1;
        }
        float md = 3.402823e38f;
#pragma unroll
        for (int p = 0; p < 22; p++){
            float dx = px - pt_s[tid*PTS + 2*p], dy = py - pt_s[tid*PTS + 2*p + 1];
            md = fminf(md, fmaf(dx,dx,dy*dy));
        }
        clo_s[tid] = sqrtf(md);
        px_s[tid] = px; py_s[tid] = py;
    }

    u64 acc[2][4];
#pragma unroll
    for (int rp=0;rp<2;rp++)
#pragma unroll
        for (int g=0;g<4;g++) acc[rp][g] = 0ULL;

    if (t > 0){
        for (int c = 0; c < 4; c++){
            if (c < 3){
                int buf = (c+1)&1;
#pragma unroll
                for (int i = 0; i < 4; i++){
                    int li = tid + i*512;
                    cpa16(wb_a + (buf*WB_CH + li*4)*4,
                          wsrc + (size_t)(c+1)*WB_CH + li*4);
                }
#pragma unroll
                for (int i = 0; i < 2; i++){
                    int li = tid + i*512;
                    int k = li >> 4, c4 = li & 15;
                    cpa16(hb_a + (buf*HB_CH + k*64 + c4*4)*4,
                          hT + (size_t)((c+1)*64 + k)*1024 + c4*4);
                }
                cpa_commit();
                cpa_wait<1>();
            } else {
                cpa_wait<0>();
            }
            __syncthreads();

            const float* hbase = hb + (c&1)*HB_CH + rb*4;
            const float* wbase = wb + (c&1)*WB_CH + u*4;
#pragma unroll 8
            for (int kk = 0; kk < 64; kk++){
                ulonglong2 A = *(const ulonglong2*)(hbase + kk*64);
                float4 wv = *(const float4*)(wbase + kk*128);
                u64 w0 = pack2(wv.x, wv.x), w1 = pack2(wv.y, wv.y);
                u64 w2 = pack2(wv.z, wv.z), w3 = pack2(wv.w, wv.w);
                acc[0][0] = fma2(A.x, w0, acc[0][0]);
                acc[0][1] = fma2(A.x, w1, acc[0][1]);
                acc[0][2] = fma2(A.x, w2, acc[0][2]);
                acc[0][3] = fma2(A.x, w3, acc[0][3]);
                acc[1][0] = fma2(A.y, w0, acc[1][0]);
                acc[1][1] = fma2(A.y, w1, acc[1][1]);
                acc[1][2] = fma2(A.y, w2, acc[1][2]);
                acc[1][3] = fma2(A.y, w3, acc[1][3]);
            }
            __syncthreads();
        }
    } else {
        __syncthreads();
    }

    {
        size_t cxbase = ((size_t)((h*16 + bm)*512 + tid))*4;
        float cx[4];
        if (t > 0){
            float4 c0 = __ldcg((const float4*)&g_cx[cxbase]);
            cx[0]=c0.x; cx[1]=c0.y; cx[2]=c0.z; cx[3]=c0.w;
        } else {
#pragma unroll
            for (int r = 0; r < 4; r++) cx[r] = 0.f;
        }
#pragma unroll
        for (int r = 0; r < 4; r++){
            int row = rb*4 + r;
            float clo = clo_s[row], ppx = px_s[row], ppy = py_s[row];
            float lo0, hi0, lo1, hi1, lo2, hi2, lo3, hi3;
            unpack2(acc[r>>1][0], lo0, hi0);
            unpack2(acc[r>>1][1], lo1, hi1);
            unpack2(acc[r>>1][2], lo2, hi2);
            unpack2(acc[r>>1][3], lo3, hi3);
            float gi = (r&1) ? hi0 : lo0;
            float gf = (r&1) ? hi1 : lo1;
            float gg = (r&1) ? hi2 : lo2;
            float go = (r&1) ? hi3 : lo3;
            gi += xv[r].x + clo*cw[0][0] + ppx*cw[1][0] + ppy*cw[2][0];
            gf += xv[r].y + clo*cw[0][1] + ppx*cw[1][1] + ppy*cw[2][1];
            gg += xv[r].z + clo*cw[0][2] + ppx*cw[1][2] + ppy*cw[2][2];
            go += xv[r].w + clo*cw[0][3] + ppx*cw[1][3] + ppy*cw[2][3];
            float c2 = sigmoidf_(gf)*cx[r] + sigmoidf_(gi)*tanhf(gg);
            float h2 = sigmoidf_(go)*tanhf(c2);
            cx[r] = c2;
            epi[row*33 + u] = h2;
        }
        *(float4*)&g_cx[cxbase] = make_float4(cx[0],cx[1],cx[2],cx[3]);
    }
    __syncthreads();

    {
        float* hout = g_hseq + ((size_t)t*NBATCH + bm*64)*256 + h*32;
#pragma unroll
        for (int i = 0; i < 4; i++){
            int li = tid + i*512;
            int row = li >> 5, c = li & 31;
            hout[row*256 + c] = epi[row*33 + c];
        }
    }
    {
        float* hT2 = g_hseqT[t&1] + bm*64;
#pragma unroll
        for (int i = 0; i < 4; i++){
            int li = tid + i*512;
            int col = li >> 6, row = li & 63;
            hT2[(size_t)(h*32 + col)*1024 + row] = epi[row*33 + col];
        }
    }
    if (tid < 64){
        int bg = bm*64 + tid;
        float px = 0.f, py = 0.f;
#pragma unroll
        for (int uu = 0; uu < 32; uu++){
            float hv = epi[tid*33 + uu];
            px = fmaf(hv, wo_s[2*uu],   px);
            py = fmaf(hv, wo_s[2*uu+1], py);
        }
        *(float2*)&g_predpart[t&1][((size_t)h*NBATCH + bg)*2] = make_float2(px, py);
    }
}

/* ================= Kernel 4: output head GEMM ================= */
__global__ void __launch_bounds__(256) out_kernel(
    const float* __restrict__ W_out, const float* __restrict__ b_out,
    const float* __restrict__ pitch, float* __restrict__ out)
{
    size_t r0 = (size_t)blockIdx.x * 64;
    int tid = threadIdx.x;
    int tx = tid & 15, ty = tid >> 4;

    __shared__ float a_s[32*68];
    __shared__ float w_s[32*96];

    float acc[4][6];
#pragma unroll
    for (int bi=0;bi<4;bi++)
#pragma unroll
        for (int ci=0;ci<6;ci++) acc[bi][ci]=0.f;

    for (int k0 = 0; k0 < 256; k0 += 32){
#pragma unroll
        for (int i = 0; i < 8; i++){
            int li = tid + i*256;
            int kk = li & 31, row = li >> 5;
            size_t r = r0 + row;
            int t = (int)(r % NSEQ), b = (int)(r / NSEQ);
            a_s[kk*68 + row] = g_hseq[((size_t)t*NBATCH + b)*256 + k0 + kk];
        }
#pragma unroll
        for (int i = 0; i < 12; i++){
            int li = tid + i*256;
            int n = li % 96, kk = li / 96;
            w_s[kk*96 + n] = (n < 90) ? W_out[(k0+kk)*90 + n] : 0.f;
        }
        __syncthreads();
#pragma unroll
        for (int kk = 0; kk < 32; kk++){
            float4 a = *(const float4*)&a_s[kk*68 + 4*ty];
            float w[6];
#pragma unroll
            for (int ci = 0; ci < 6; ci++) w[ci] = w_s[kk*96 + 6*tx + ci];
#pragma unroll
            for (int ci = 0; ci < 6; ci++){
                acc[0][ci] = fmaf(a.x, w[ci], acc[0][ci]);
                acc[1][ci] = fmaf(a.y, w[ci], acc[1][ci]);
                acc[2][ci] = fmaf(a.z, w[ci], acc[2][ci]);
                acc[3][ci] = fmaf(a.w, w[ci], acc[3][ci]);
            }
        }
        __syncthreads();
    }
#pragma unroll
    for (int bi = 0; bi < 4; bi++){
        size_t r = r0 + 4*ty + bi;
#pragma unroll
        for (int ci = 0; ci < 6; ci++){
            int n = 6*tx + ci;
            if (n < 90)
                out[r*90 + n] = (acc[bi][ci] + b_out[n]) * pitch[n & 1];
        }
    }
}

/* ================= host launcher ================= */
extern "C" void kernel_launch(void* const* d_in, const int* in_sizes, int n_in,
                              void* d_out, int out_size)
{
    const float* coords = (const float*)d_in[0];
    const float* pitch  = (const float*)d_in[1];
    const float* W_e1   = (const float*)d_in[2];
    const float* b_e1   = (const float*)d_in[3];
    const float* W_e2   = (const float*)d_in[4];
    const float* b_e2   = (const float*)d_in[5];
    const float* W_ih   = (const float*)d_in[6];
    const float* b_ih   = (const float*)d_in[7];
    const float* W_hh   = (const float*)d_in[8];
    const float* b_hh   = (const float*)d_in[9];
    const float* W_out  = (const float*)d_in[10];
    const float* b_out  = (const float*)d_in[11];
    float* out = (float*)d_out;

    size_t xpre_smem = (size_t)XPRE_SMEM_FLOATS * sizeof(float);   /* 98,304 B */
    size_t rnn_smem  = (size_t)RNN_SMEM_FLOATS * sizeof(float);    /* ~111 KB  */
    static int attr_done = 0;
    if (!attr_done){
        cudaFuncSetAttribute(xpre_kernel, cudaFuncAttributeMaxDynamicSharedMemorySize,
                             (int)xpre_smem);
        cudaFuncSetAttribute(rnn_step_kernel, cudaFuncAttributeMaxDynamicSharedMemorySize,
                             (int)rnn_smem);
        attr_done = 1;
    }

    prep_kernel<<<256, 256>>>(W_hh, W_out, W_ih, b_ih, b_hh);
    tcoords_kernel<<<dim3(400, 64), 512>>>(coords);
    enc_kernel<<<NROWS/4, 256>>>(coords, W_e1, b_e1, W_e2, b_e2);
    xpre_kernel<<<dim3(8, NROWS/64), 512, xpre_smem>>>();

    for (int t = 0; t < NSEQ; t++)
        rnn_step_kernel<<<dim3(8,16), 512, rnn_smem>>>(coords, W_ih, b_out, pitch, t);

    out_kernel<<<NROWS/64, 256>>>(W_out, b_out, pitch, out);
}